// round 11
// baseline (speedup 1.0000x reference)
#include <cuda_runtime.h>
#include <math.h>

#define HOP 160
#define NFFT 512
#define NMEL 64
#define NFREQ 257
#define PREEMPH 0.97f
#define LOG_GUARD 5.9604644775390625e-8f   // 2^-24

#define MAXB 32
#define MAXT 1601
#define WPB 8                      // frames (warps) per block
#define SEG (HOP * (WPB - 1) + NFFT)   // 1632 staged samples per block

struct MelRanges { int lo[NMEL]; int hi[NMEL]; };

// ---- device scratch (no allocations allowed; zero-init at load, self-cleaning) ----
__device__ float  g_mean[MAXB * NMEL];
__device__ float  g_rstd[MAXB * NMEL];
__device__ double g_sum[MAXB * NMEL];
__device__ double g_ssum[MAXB * NMEL];
__device__ int    g_cnt[MAXB];
__device__ __align__(16) float g_logmel[(size_t)MAXB * MAXT * NMEL];  // [b*T+t, m]

// ---------------------------------------------------------------------------
// frame kernel: block = 8 consecutive frames of one batch row, register FFT,
// fused masked stats (atomics + per-b last-block finalize, self-cleaning).
// ---------------------------------------------------------------------------
__global__ __launch_bounds__(32 * WPB) void frame_kernel(
    const float* __restrict__ x, const float* __restrict__ win,
    const float* __restrict__ fb, const int* __restrict__ seq_len,
    int L, int T, int nchunk, MelRanges mr)
{
    __shared__ float  sy[SEG];
    __shared__ float2 wsh[256];
    __shared__ float  sh_re[WPB][288];   // idx + (idx>>3) padding
    __shared__ float  sh_im[WPB][288];
    __shared__ float  sh_pow[WPB][264];
    __shared__ float  sh_lm[WPB][NMEL];  // logmel staging for stats
    __shared__ int    s_lo[NMEL], s_hi[NMEL];
    __shared__ int    s_last;

    const int tid = threadIdx.x;
    const int b = blockIdx.x / nchunk;
    const int chunk = blockIdx.x - b * nchunk;
    const int t0 = chunk * WPB;
    const float* xb = x + (size_t)b * L;
    const int base0 = t0 * HOP - (NFFT / 2);
    const int flen = seq_len[b] / HOP + 1;

    const float2* win2 = (const float2*)win;
    for (int i = tid; i < 256; i += 32 * WPB) wsh[i] = win2[i];
    if (tid < NMEL) { s_lo[tid] = mr.lo[tid]; s_hi[tid] = mr.hi[tid]; }

    // ---- stage input segment: y[n] = preemph(x)[reflect(n)] ----
    if (base0 >= 1 && base0 + SEG <= L) {
        #pragma unroll
        for (int r = 0; r < 7; r++) {
            int i = tid + r * 256;
            if (i < SEG) {
                int n = base0 + i;
                sy[i] = xb[n] - PREEMPH * xb[n - 1];
            }
        }
    } else {
        #pragma unroll
        for (int r = 0; r < 7; r++) {
            int i = tid + r * 256;
            if (i < SEG) {
                int n = base0 + i;
                int q = n < 0 ? -n : n;
                if (q >= L) q = 2 * (L - 1) - q;
                sy[i] = (q == 0) ? xb[0] : (xb[q] - PREEMPH * xb[q - 1]);
            }
        }
    }
    __syncthreads();

    const int wid = tid >> 5;
    const int lane = tid & 31;
    const int t = t0 + wid;
    const bool valid = (t < T);
    const int fid = b * T + t;

    // ---- pack from shared: z[k] = y(2k) + i*y(2k+1), windowed ----
    float zr[8], zi[8];
    const float2* sy2 = (const float2*)sy;
    const int sb = 80 * wid;
    #pragma unroll
    for (int p = 0; p < 8; p++) {
        int k = lane + 32 * p;
        float2 w2 = wsh[k];
        float2 v = sy2[sb + k];
        zr[p] = w2.x * v.x;
        zi[p] = w2.y * v.y;
    }

    // ---- per-lane DFT8 over p (DIF, constant twiddles) ----
    {
        const float C = 0.70710678118654752f;
        float tr[4], ti[4], ur[4], ui[4];
        #pragma unroll
        for (int p = 0; p < 4; p++) {
            tr[p] = zr[p] + zr[p + 4];  ti[p] = zi[p] + zi[p + 4];
            ur[p] = zr[p] - zr[p + 4];  ui[p] = zi[p] - zi[p + 4];
        }
        { float a = ur[1], bq = ui[1]; ur[1] = C * (a + bq); ui[1] = C * (bq - a); }
        { float a = ur[2], bq = ui[2]; ur[2] = bq; ui[2] = -a; }
        { float a = ur[3], bq = ui[3]; ur[3] = C * (bq - a); ui[3] = -C * (a + bq); }
        float ar = tr[0] + tr[2], ai = ti[0] + ti[2];
        float br = tr[0] - tr[2], bi = ti[0] - ti[2];
        float cr = tr[1] + tr[3], ci = ti[1] + ti[3];
        float dr = ti[1] - ti[3], di = -(tr[1] - tr[3]);
        zr[0] = ar + cr; zi[0] = ai + ci;
        zr[4] = ar - cr; zi[4] = ai - ci;
        zr[2] = br + dr; zi[2] = bi + di;
        zr[6] = br - dr; zi[6] = bi - di;
        ar = ur[0] + ur[2]; ai = ui[0] + ui[2];
        br = ur[0] - ur[2]; bi = ui[0] - ui[2];
        cr = ur[1] + ur[3]; ci = ui[1] + ui[3];
        dr = ui[1] - ui[3]; di = -(ur[1] - ur[3]);
        zr[1] = ar + cr; zi[1] = ai + ci;
        zr[5] = ar - cr; zi[5] = ai - ci;
        zr[3] = br + dr; zi[3] = bi + di;
        zr[7] = br - dr; zi[7] = bi - di;
    }

    // ---- per-lane twiddle: A[k1] *= exp(-2*pi*i*lane*k1/256) via chain ----
    {
        float s1, c1;
        sincospif((float)lane / 128.0f, &s1, &c1);
        float w1r = c1, w1i = -s1;
        float wr = w1r, wi = w1i;
        #pragma unroll
        for (int k1 = 1; k1 < 8; k1++) {
            float nr = zr[k1] * wr - zi[k1] * wi;
            zi[k1]   = zr[k1] * wi + zi[k1] * wr;
            zr[k1]   = nr;
            float nwr = wr * w1r - wi * w1i;
            wi = wr * w1i + wi * w1r;
            wr = nwr;
        }
    }

    // ---- 32-pt cross-lane FFT: unified branch-free butterflies ----
    #pragma unroll
    for (int st = 0; st < 4; st++) {
        int h = 16 >> st;
        bool up = (lane & h) != 0;
        float sg = up ? -1.0f : 1.0f;
        int j = lane & (h - 1);
        float ss, cc;
        sincospif((float)j / (float)h, &ss, &cc);
        float wr = up ? cc : 1.0f;
        float wi = up ? -ss : 0.0f;
        #pragma unroll
        for (int k1 = 0; k1 < 8; k1++) {
            float pr = __shfl_xor_sync(0xFFFFFFFFu, zr[k1], h);
            float pi = __shfl_xor_sync(0xFFFFFFFFu, zi[k1], h);
            float dr = fmaf(sg, zr[k1], pr);
            float di = fmaf(sg, zi[k1], pi);
            zr[k1] = dr * wr - di * wi;
            zi[k1] = dr * wi + di * wr;
        }
    }
    {   // h = 1: twiddle is identity
        float sg = (lane & 1) ? -1.0f : 1.0f;
        #pragma unroll
        for (int k1 = 0; k1 < 8; k1++) {
            float pr = __shfl_xor_sync(0xFFFFFFFFu, zr[k1], 1);
            float pi = __shfl_xor_sync(0xFFFFFFFFu, zi[k1], 1);
            zr[k1] = fmaf(sg, zr[k1], pr);
            zi[k1] = fmaf(sg, zi[k1], pi);
        }
    }
    // lane holds X[k1 + 8*bitrev5(lane)]

    // ---- store Z to padded shared (conflict-free: 9*rev is odd-stride) ----
    {
        int rev = __brev(lane) >> 27;
        int a0 = 9 * rev;
        #pragma unroll
        for (int k1 = 0; k1 < 8; k1++) {
            sh_re[wid][a0 + k1] = zr[k1];
            sh_im[wid][a0 + k1] = zi[k1];
        }
    }
    __syncwarp();

    // ---- paired real-FFT split + power spectrum ----
    {
        float bs, bc;
        sincospif((float)lane / 256.0f, &bs, &bc);
        float wr = bc, wi = -bs;                       // exp(-i*pi*f/256), f=lane
        const float STC = 0.92387953251128674f;        // cos(pi/8)
        const float STS = -0.38268343236508977f;       // -sin(pi/8)
        #pragma unroll
        for (int r = 0; r < 4; r++) {
            int f = lane + 32 * r;                     // 0..127
            int g = 256 - f;                           // 129..256
            float zfr = sh_re[wid][f + (f >> 3)], zfi = sh_im[wid][f + (f >> 3)];
            float zgr = sh_re[wid][g + (g >> 3)], zgi = sh_im[wid][g + (g >> 3)];
            float er = 0.5f * (zfr + zgr);
            float ei = 0.5f * (zfi - zgi);
            float orr = 0.5f * (zfi + zgi);
            float oi  = -0.5f * (zfr - zgr);
            float ur = wr * orr - wi * oi;
            float ui = wr * oi + wi * orr;
            float ar = er + ur, ai = ei + ui;
            float br = er - ur, bi = ei - ui;
            sh_pow[wid][f] = fmaf(ar, ar, ai * ai);
            sh_pow[wid][g] = fmaf(br, br, bi * bi);
            float nr = wr * STC - wi * STS;
            wi = wr * STS + wi * STC;
            wr = nr;
        }
        if (lane == 0) {
            float hr = sh_re[wid][144], hi = sh_im[wid][144];  // Z[128] (padded)
            sh_pow[wid][128] = fmaf(hr, hr, hi * hi);
        }
    }
    __syncwarp();

    // ---- sparse mel projection + log (width-balanced: lane, 63-lane) ----
    {
        const bool mask = valid && (t < flen);
        float* pw = sh_pow[wid];
        float* outp = g_logmel + (size_t)fid * NMEL;
        #pragma unroll
        for (int mm = 0; mm < 2; mm++) {
            int m = mm ? (63 - lane) : lane;
            int lo = s_lo[m], hi = s_hi[m];
            float acc = 0.0f;
            const float* frow = fb + m * NFREQ;
            int f = lo;
            for (; f + 3 <= hi; f += 4) {
                acc = fmaf(__ldg(frow + f),     pw[f],     acc);
                acc = fmaf(__ldg(frow + f + 1), pw[f + 1], acc);
                acc = fmaf(__ldg(frow + f + 2), pw[f + 2], acc);
                acc = fmaf(__ldg(frow + f + 3), pw[f + 3], acc);
            }
            for (; f <= hi; f++) acc = fmaf(__ldg(frow + f), pw[f], acc);
            float v = __logf(acc + LOG_GUARD);
            if (valid) outp[m] = v;
            sh_lm[wid][m] = mask ? v : 0.0f;
        }
    }
    __syncthreads();

    // ---- fused stats: block partials -> double atomics ----
    if (tid < NMEL) {
        double s = 0.0, ss = 0.0;
        #pragma unroll
        for (int w = 0; w < WPB; w++) {
            double v = (double)sh_lm[w][tid];
            s += v;
            ss += v * v;
        }
        atomicAdd(&g_sum[b * NMEL + tid], s);
        atomicAdd(&g_ssum[b * NMEL + tid], ss);
    }
    __threadfence();
    __syncthreads();
    if (tid == 0) {
        int prev = atomicAdd(&g_cnt[b], 1);
        s_last = (prev == nchunk - 1) ? 1 : 0;
    }
    __syncthreads();
    if (s_last) {
        if (tid < NMEL) {
            double ds = g_sum[b * NMEL + tid];
            double dss = g_ssum[b * NMEL + tid];
            double n = (double)flen;
            double mean = ds / n;
            double var = (dss - ds * ds / n) / (n - 1.0);
            if (var < 0.0) var = 0.0;
            double std = sqrt(var) + 1e-5;
            g_mean[b * NMEL + tid] = (float)mean;
            g_rstd[b * NMEL + tid] = (float)(1.0 / std);
            // self-clean for next graph replay
            g_sum[b * NMEL + tid] = 0.0;
            g_ssum[b * NMEL + tid] = 0.0;
        }
        if (tid == 0) g_cnt[b] = 0;
    }
}

// ---------------------------------------------------------------------------
// normalize + transpose [b,t,m] -> [b,m,t], zero masked/pad frames
// ---------------------------------------------------------------------------
__global__ __launch_bounds__(256) void out_kernel(
    const int* __restrict__ seq_len, float* __restrict__ out,
    int T, int TP, int extra)
{
    __shared__ float tile[64 * 65];
    __shared__ float mu[64];
    __shared__ float rs[64];

    int tid = threadIdx.x;
    int b = blockIdx.y;
    int t0 = blockIdx.x * 64;
    int flen = seq_len[b] / HOP + 1;

    if (tid < 64) {
        mu[tid] = g_mean[b * NMEL + tid];
        rs[tid] = g_rstd[b * NMEL + tid];
    }
    __syncthreads();

    #pragma unroll
    for (int r = 0; r < 16; r++) {
        int idx = r * 256 + tid;
        int m = idx & 63;
        int tl = idx >> 6;
        int t = t0 + tl;
        float v = 0.0f;
        if (t < flen) {
            v = (g_logmel[((size_t)(b * T + t)) * NMEL + m] - mu[m]) * rs[m];
        }
        tile[tl * 65 + m] = v;
    }
    __syncthreads();

    #pragma unroll
    for (int r = 0; r < 16; r++) {
        int idx = r * 256 + tid;
        int tl = idx & 63;
        int m = idx >> 6;
        int t = t0 + tl;
        if (t < TP) out[((size_t)b * NMEL + m) * TP + t] = tile[tl * 65 + m];
    }

    if (blockIdx.x == 0 && tid == 0 && b < extra) {
        size_t tail = (size_t)gridDim.y * NMEL * TP;
        out[tail + b] = (float)flen;
    }
}

// ---------------------------------------------------------------------------
// host: slaney mel filter support ranges (pure math; ±1 bin slack)
// ---------------------------------------------------------------------------
static void compute_mel_ranges(MelRanges* mr) {
    const double f_sp = 200.0 / 3.0;
    const double min_log_hz = 1000.0;
    const double min_log_mel = min_log_hz / f_sp;
    const double logstep = log(6.4) / 27.0;
    const double fmax = 8000.0;
    const double m_max = min_log_mel + log(fmax / min_log_hz) / logstep;
    double f_pts[NMEL + 2];
    for (int i = 0; i < NMEL + 2; i++) {
        double m = m_max * (double)i / (double)(NMEL + 1);
        f_pts[i] = (m >= min_log_mel)
                     ? min_log_hz * exp(logstep * (m - min_log_mel))
                     : f_sp * m;
    }
    const double df = 8000.0 / 256.0;    // bin spacing
    for (int m = 0; m < NMEL; m++) {
        double fl = f_pts[m], fr = f_pts[m + 2];
        int lo = (int)floor(fl / df) + 1;   // first bin with f_k > fl
        int hi = (int)ceil(fr / df) - 1;    // last bin with f_k < fr
        lo -= 1; hi += 1;                   // slack for float rounding
        if (lo < 0) lo = 0;
        if (hi > NFREQ - 1) hi = NFREQ - 1;
        if (hi < lo) hi = lo;
        mr->lo[m] = lo;
        mr->hi[m] = hi;
    }
}

// ---------------------------------------------------------------------------
extern "C" void kernel_launch(void* const* d_in, const int* in_sizes, int n_in,
                              void* d_out, int out_size)
{
    const float* x   = (const float*)d_in[0];
    const int*   seq = (const int*)d_in[1];
    const float* win = (const float*)d_in[2];
    const float* fb  = (const float*)d_in[3];
    float* out = (float*)d_out;

    int B = in_sizes[1];
    int L = in_sizes[0] / B;
    int T = L / HOP + 1;
    int TP = ((T + 15) / 16) * 16;

    MelRanges mr;
    compute_mel_ranges(&mr);

    int nchunk_f = (T + WPB - 1) / WPB;
    frame_kernel<<<B * nchunk_f, 32 * WPB>>>(x, win, fb, seq, L, T, nchunk_f, mr);

    int nchunk = (TP + 63) / 64;
    long long extra = (long long)out_size - (long long)B * NMEL * TP;
    int ex = extra > 0 ? (int)(extra < B ? extra : B) : 0;
    out_kernel<<<dim3(nchunk, B), 256>>>(seq, out, T, TP, ex);
}

// round 14
// speedup vs baseline: 1.0658x; 1.0658x over previous
#include <cuda_runtime.h>
#include <math.h>

#define HOP 160
#define NFFT 512
#define NMEL 64
#define NFREQ 257
#define PREEMPH 0.97f
#define LOG_GUARD 5.9604644775390625e-8f   // 2^-24

#define MAXB 32
#define MAXT 1601
#define WPB 8                      // frames (warps) per block
#define SEG (HOP * (WPB - 1) + NFFT)   // 1632 staged samples per block

struct MelRanges { int lo[NMEL]; int hi[NMEL]; };

// ---- device scratch (no allocations; overwrite-only => replay-safe) ----
__device__ float  g_mean[MAXB * NMEL];
__device__ float  g_rstd[MAXB * NMEL];
__device__ __align__(16) float g_logmel[(size_t)MAXB * MAXT * NMEL];  // [b*T+t, m]

// ---------------------------------------------------------------------------
// frame kernel: block = 8 consecutive frames of one batch row (R5 core).
// ---------------------------------------------------------------------------
__global__ __launch_bounds__(32 * WPB) void frame_kernel(
    const float* __restrict__ x, const float* __restrict__ win,
    const float* __restrict__ fb, int L, int T, int nchunk, MelRanges mr)
{
    __shared__ float  sy[SEG];
    __shared__ float2 wsh[256];
    __shared__ float  sh_re[WPB][288];   // idx + (idx>>3) padding
    __shared__ float  sh_im[WPB][288];
    __shared__ float  sh_pow[WPB][264];
    __shared__ int    s_lo[NMEL], s_hi[NMEL];

    const int tid = threadIdx.x;
    const int b = blockIdx.x / nchunk;
    const int chunk = blockIdx.x - b * nchunk;
    const int t0 = chunk * WPB;
    const float* xb = x + (size_t)b * L;
    const int base0 = t0 * HOP - (NFFT / 2);

    const float2* win2 = (const float2*)win;
    for (int i = tid; i < 256; i += 32 * WPB) wsh[i] = win2[i];
    if (tid < NMEL) { s_lo[tid] = mr.lo[tid]; s_hi[tid] = mr.hi[tid]; }

    // ---- stage input segment: y[n] = preemph(x)[reflect(n)] ----
    if (base0 >= 1 && base0 + SEG <= L) {
        #pragma unroll
        for (int r = 0; r < 7; r++) {
            int i = tid + r * 256;
            if (i < SEG) {
                int n = base0 + i;
                sy[i] = xb[n] - PREEMPH * xb[n - 1];
            }
        }
    } else {
        #pragma unroll
        for (int r = 0; r < 7; r++) {
            int i = tid + r * 256;
            if (i < SEG) {
                int n = base0 + i;
                int q = n < 0 ? -n : n;
                if (q >= L) q = 2 * (L - 1) - q;
                sy[i] = (q == 0) ? xb[0] : (xb[q] - PREEMPH * xb[q - 1]);
            }
        }
    }
    __syncthreads();

    const int wid = tid >> 5;
    const int lane = tid & 31;
    const int t = t0 + wid;
    if (t >= T) return;
    const int fid = b * T + t;

    // ---- pack from shared: z[k] = y(2k) + i*y(2k+1), windowed ----
    float zr[8], zi[8];
    const float2* sy2 = (const float2*)sy;
    const int sb = 80 * wid;
    #pragma unroll
    for (int p = 0; p < 8; p++) {
        int k = lane + 32 * p;
        float2 w2 = wsh[k];
        float2 v = sy2[sb + k];
        zr[p] = w2.x * v.x;
        zi[p] = w2.y * v.y;
    }

    // ---- per-lane DFT8 over p (DIF, constant twiddles) ----
    {
        const float C = 0.70710678118654752f;
        float tr[4], ti[4], ur[4], ui[4];
        #pragma unroll
        for (int p = 0; p < 4; p++) {
            tr[p] = zr[p] + zr[p + 4];  ti[p] = zi[p] + zi[p + 4];
            ur[p] = zr[p] - zr[p + 4];  ui[p] = zi[p] - zi[p + 4];
        }
        { float a = ur[1], bq = ui[1]; ur[1] = C * (a + bq); ui[1] = C * (bq - a); }
        { float a = ur[2], bq = ui[2]; ur[2] = bq; ui[2] = -a; }
        { float a = ur[3], bq = ui[3]; ur[3] = C * (bq - a); ui[3] = -C * (a + bq); }
        float ar = tr[0] + tr[2], ai = ti[0] + ti[2];
        float br = tr[0] - tr[2], bi = ti[0] - ti[2];
        float cr = tr[1] + tr[3], ci = ti[1] + ti[3];
        float dr = ti[1] - ti[3], di = -(tr[1] - tr[3]);
        zr[0] = ar + cr; zi[0] = ai + ci;
        zr[4] = ar - cr; zi[4] = ai - ci;
        zr[2] = br + dr; zi[2] = bi + di;
        zr[6] = br - dr; zi[6] = bi - di;
        ar = ur[0] + ur[2]; ai = ui[0] + ui[2];
        br = ur[0] - ur[2]; bi = ui[0] - ui[2];
        cr = ur[1] + ur[3]; ci = ui[1] + ui[3];
        dr = ui[1] - ui[3]; di = -(ur[1] - ur[3]);
        zr[1] = ar + cr; zi[1] = ai + ci;
        zr[5] = ar - cr; zi[5] = ai - ci;
        zr[3] = br + dr; zi[3] = bi + di;
        zr[7] = br - dr; zi[7] = bi - di;
    }

    // ---- per-lane twiddle: A[k1] *= exp(-2*pi*i*lane*k1/256) via chain ----
    {
        float s1, c1;
        sincospif((float)lane / 128.0f, &s1, &c1);
        float w1r = c1, w1i = -s1;
        float wr = w1r, wi = w1i;
        #pragma unroll
        for (int k1 = 1; k1 < 8; k1++) {
            float nr = zr[k1] * wr - zi[k1] * wi;
            zi[k1]   = zr[k1] * wi + zi[k1] * wr;
            zr[k1]   = nr;
            float nwr = wr * w1r - wi * w1i;
            wi = wr * w1i + wi * w1r;
            wr = nwr;
        }
    }

    // ---- 32-pt cross-lane FFT: unified branch-free butterflies ----
    #pragma unroll
    for (int st = 0; st < 4; st++) {
        int h = 16 >> st;
        bool up = (lane & h) != 0;
        float sg = up ? -1.0f : 1.0f;
        int j = lane & (h - 1);
        float ss, cc;
        sincospif((float)j / (float)h, &ss, &cc);
        float wr = up ? cc : 1.0f;
        float wi = up ? -ss : 0.0f;
        #pragma unroll
        for (int k1 = 0; k1 < 8; k1++) {
            float pr = __shfl_xor_sync(0xFFFFFFFFu, zr[k1], h);
            float pi = __shfl_xor_sync(0xFFFFFFFFu, zi[k1], h);
            float dr = fmaf(sg, zr[k1], pr);
            float di = fmaf(sg, zi[k1], pi);
            zr[k1] = dr * wr - di * wi;
            zi[k1] = dr * wi + di * wr;
        }
    }
    {   // h = 1: twiddle is identity
        float sg = (lane & 1) ? -1.0f : 1.0f;
        #pragma unroll
        for (int k1 = 0; k1 < 8; k1++) {
            float pr = __shfl_xor_sync(0xFFFFFFFFu, zr[k1], 1);
            float pi = __shfl_xor_sync(0xFFFFFFFFu, zi[k1], 1);
            zr[k1] = fmaf(sg, zr[k1], pr);
            zi[k1] = fmaf(sg, zi[k1], pi);
        }
    }
    // lane holds X[k1 + 8*bitrev5(lane)]

    // ---- store Z to padded shared (conflict-free: 9*rev is odd-stride) ----
    {
        int rev = __brev(lane) >> 27;
        int a0 = 9 * rev;
        #pragma unroll
        for (int k1 = 0; k1 < 8; k1++) {
            sh_re[wid][a0 + k1] = zr[k1];
            sh_im[wid][a0 + k1] = zi[k1];
        }
    }
    __syncwarp();

    // ---- paired real-FFT split + power spectrum ----
    {
        float bs, bc;
        sincospif((float)lane / 256.0f, &bs, &bc);
        float wr = bc, wi = -bs;                       // exp(-i*pi*f/256), f=lane
        const float STC = 0.92387953251128674f;        // cos(pi/8)
        const float STS = -0.38268343236508977f;       // -sin(pi/8)
        #pragma unroll
        for (int r = 0; r < 4; r++) {
            int f = lane + 32 * r;                     // 0..127
            int g = 256 - f;                           // 129..256
            float zfr = sh_re[wid][f + (f >> 3)], zfi = sh_im[wid][f + (f >> 3)];
            float zgr = sh_re[wid][g + (g >> 3)], zgi = sh_im[wid][g + (g >> 3)];
            float er = 0.5f * (zfr + zgr);
            float ei = 0.5f * (zfi - zgi);
            float orr = 0.5f * (zfi + zgi);
            float oi  = -0.5f * (zfr - zgr);
            float ur = wr * orr - wi * oi;
            float ui = wr * oi + wi * orr;
            float ar = er + ur, ai = ei + ui;
            float br = er - ur, bi = ei - ui;
            sh_pow[wid][f] = fmaf(ar, ar, ai * ai);
            sh_pow[wid][g] = fmaf(br, br, bi * bi);
            float nr = wr * STC - wi * STS;
            wi = wr * STS + wi * STC;
            wr = nr;
        }
        if (lane == 0) {
            float hr = sh_re[wid][144], hi = sh_im[wid][144];  // Z[128] (padded)
            sh_pow[wid][128] = fmaf(hr, hr, hi * hi);
        }
    }
    __syncwarp();

    // ---- sparse mel projection + log (width-balanced: lane, 63-lane) ----
    {
        float* pw = sh_pow[wid];
        float* outp = g_logmel + (size_t)fid * NMEL;
        #pragma unroll
        for (int mm = 0; mm < 2; mm++) {
            int m = mm ? (63 - lane) : lane;
            int lo = s_lo[m], hi = s_hi[m];
            float acc = 0.0f;
            const float* frow = fb + m * NFREQ;
            int f = lo;
            for (; f + 3 <= hi; f += 4) {
                acc = fmaf(__ldg(frow + f),     pw[f],     acc);
                acc = fmaf(__ldg(frow + f + 1), pw[f + 1], acc);
                acc = fmaf(__ldg(frow + f + 2), pw[f + 2], acc);
                acc = fmaf(__ldg(frow + f + 3), pw[f + 3], acc);
            }
            for (; f <= hi; f++) acc = fmaf(__ldg(frow + f), pw[f], acc);
            outp[m] = __logf(acc + LOG_GUARD);
        }
    }
}

// ---------------------------------------------------------------------------
// stats: masked mean / unbiased std per (b, m) — monolithic, overwrite-only
// ---------------------------------------------------------------------------
__global__ __launch_bounds__(1024) void stats_kernel(
    const int* __restrict__ seq_len, int T)
{
    __shared__ double sh_s[1024];
    __shared__ double sh_ss[1024];
    int b = blockIdx.x;
    int m = threadIdx.x & 63;
    int ph = threadIdx.x >> 6;      // 16 phases
    int flen = seq_len[b] / HOP + 1;

    float s = 0.0f, ss = 0.0f;
    for (int t = ph; t < flen; t += 16) {
        float v = g_logmel[((size_t)(b * T + t)) * NMEL + m];
        s += v;
        ss = fmaf(v, v, ss);
    }
    sh_s[threadIdx.x] = (double)s;
    sh_ss[threadIdx.x] = (double)ss;
    __syncthreads();
    if (ph == 0) {
        double ds = 0.0, dss = 0.0;
        #pragma unroll
        for (int i = 0; i < 16; i++) {
            ds += sh_s[m + 64 * i];
            dss += sh_ss[m + 64 * i];
        }
        double n = (double)flen;
        double mean = ds / n;
        double var = (dss - ds * ds / n) / (n - 1.0);
        if (var < 0.0) var = 0.0;
        double std = sqrt(var) + 1e-5;
        g_mean[b * NMEL + m] = (float)mean;
        g_rstd[b * NMEL + m] = (float)(1.0 / std);
    }
}

// ---------------------------------------------------------------------------
// normalize + transpose [b,t,m] -> [b,m,t], zero masked/pad frames
// ---------------------------------------------------------------------------
__global__ __launch_bounds__(256) void out_kernel(
    const int* __restrict__ seq_len, float* __restrict__ out,
    int T, int TP, int extra)
{
    __shared__ float tile[64 * 65];
    __shared__ float mu[64];
    __shared__ float rs[64];

    int tid = threadIdx.x;
    int b = blockIdx.y;
    int t0 = blockIdx.x * 64;
    int flen = seq_len[b] / HOP + 1;

    if (tid < 64) {
        mu[tid] = g_mean[b * NMEL + tid];
        rs[tid] = g_rstd[b * NMEL + tid];
    }
    __syncthreads();

    #pragma unroll
    for (int r = 0; r < 16; r++) {
        int idx = r * 256 + tid;
        int m = idx & 63;
        int tl = idx >> 6;
        int t = t0 + tl;
        float v = 0.0f;
        if (t < flen) {
            v = (g_logmel[((size_t)(b * T + t)) * NMEL + m] - mu[m]) * rs[m];
        }
        tile[tl * 65 + m] = v;
    }
    __syncthreads();

    #pragma unroll
    for (int r = 0; r < 16; r++) {
        int idx = r * 256 + tid;
        int tl = idx & 63;
        int m = idx >> 6;
        int t = t0 + tl;
        if (t < TP) out[((size_t)b * NMEL + m) * TP + t] = tile[tl * 65 + m];
    }

    if (blockIdx.x == 0 && tid == 0 && b < extra) {
        size_t tail = (size_t)gridDim.y * NMEL * TP;
        out[tail + b] = (float)flen;
    }
}

// ---------------------------------------------------------------------------
// host: slaney mel filter support ranges (pure math; ±1 bin slack)
// ---------------------------------------------------------------------------
static void compute_mel_ranges(MelRanges* mr) {
    const double f_sp = 200.0 / 3.0;
    const double min_log_hz = 1000.0;
    const double min_log_mel = min_log_hz / f_sp;
    const double logstep = log(6.4) / 27.0;
    const double fmax = 8000.0;
    const double m_max = min_log_mel + log(fmax / min_log_hz) / logstep;
    double f_pts[NMEL + 2];
    for (int i = 0; i < NMEL + 2; i++) {
        double m = m_max * (double)i / (double)(NMEL + 1);
        f_pts[i] = (m >= min_log_mel)
                     ? min_log_hz * exp(logstep * (m - min_log_mel))
                     : f_sp * m;
    }
    const double df = 8000.0 / 256.0;    // bin spacing
    for (int m = 0; m < NMEL; m++) {
        double fl = f_pts[m], fr = f_pts[m + 2];
        int lo = (int)floor(fl / df) + 1;
        int hi = (int)ceil(fr / df) - 1;
        lo -= 1; hi += 1;                 // slack for float rounding
        if (lo < 0) lo = 0;
        if (hi > NFREQ - 1) hi = NFREQ - 1;
        if (hi < lo) hi = lo;
        mr->lo[m] = lo;
        mr->hi[m] = hi;
    }
}

// ---------------------------------------------------------------------------
extern "C" void kernel_launch(void* const* d_in, const int* in_sizes, int n_in,
                              void* d_out, int out_size)
{
    const float* x   = (const float*)d_in[0];
    const int*   seq = (const int*)d_in[1];
    const float* win = (const float*)d_in[2];
    const float* fb  = (const float*)d_in[3];
    float* out = (float*)d_out;

    int B = in_sizes[1];
    int L = in_sizes[0] / B;
    int T = L / HOP + 1;
    int TP = ((T + 15) / 16) * 16;

    MelRanges mr;
    compute_mel_ranges(&mr);

    int nchunk_f = (T + WPB - 1) / WPB;
    frame_kernel<<<B * nchunk_f, 32 * WPB>>>(x, win, fb, L, T, nchunk_f, mr);

    stats_kernel<<<B, 1024>>>(seq, T);

    int nchunk = (TP + 63) / 64;
    long long extra = (long long)out_size - (long long)B * NMEL * TP;
    int ex = extra > 0 ? (int)(extra < B ? extra : B) : 0;
    out_kernel<<<dim3(nchunk, B), 256>>>(seq, out, T, TP, ex);
}